// round 4
// baseline (speedup 1.0000x reference)
#include <cuda_runtime.h>
#include <cuda_bf16.h>
#include <cstdint>

#define EPS_F 0.01f

constexpr int B = 16;
constexpr int H = 1024;
constexpr int W = 1024;

// Each warp owns a 128-col x R-row strip; CTA = 8 warps covering full width.
constexpr int R = 16;              // rows per CTA strip
constexpr int WARPS = 8;           // 8 * 128 = 1024 = W
constexpr int THREADS = WARPS * 32;

__device__ __forceinline__ float fmax3(float a, float b, float c) {
    return fmaxf(fmaxf(a, b), c);
}

// Load one image row's 4-pixel window for this lane:
// w[0..5] = x at cols gx-1 .. gx+4 (x = c1 - c0 - EPS; out-of-image -> 0).
// Optionally stream-stores the seg copy for the 4 owned pixels.
__device__ __forceinline__ void load_row(
    const float* __restrict__ c0, const float* __restrict__ c1,
    float* __restrict__ oseg, int y, int gx, int lane, bool do_copy,
    float w[6])
{
    if ((unsigned)y >= (unsigned)H) {
        #pragma unroll
        for (int j = 0; j < 6; j++) w[j] = 0.0f;
        return;
    }
    const size_t g = (size_t)y * W + gx;
    const float4 a  = *(const float4*)(c0 + g);
    const float4 bb = *(const float4*)(c1 + g);
    if (do_copy) {
        __stcs((float4*)(oseg + g), a);
        __stcs((float4*)(oseg + (size_t)H * W + g), bb);
    }
    w[1] = bb.x - a.x - EPS_F;
    w[2] = bb.y - a.y - EPS_F;
    w[3] = bb.z - a.z - EPS_F;
    w[4] = bb.w - a.w - EPS_F;
    const unsigned FULL = 0xFFFFFFFFu;
    float lft = __shfl_up_sync(FULL, w[4], 1);    // lane-1's col gx-1
    float rgt = __shfl_down_sync(FULL, w[1], 1);  // lane+1's col gx+4
    if (lane == 0) {
        lft = 0.0f;
        if (gx - 1 >= 0) lft = __ldg(c1 + g - 1) - __ldg(c0 + g - 1) - EPS_F;
    }
    if (lane == 31) {
        rgt = 0.0f;
        if (gx + 4 < W) rgt = __ldg(c1 + g + 4) - __ldg(c0 + g + 4) - EPS_F;
    }
    w[0] = lft;
    w[5] = rgt;
}

__device__ __forceinline__ void h3_of(const float w[6], float h3[4]) {
    #pragma unroll
    for (int i = 0; i < 4; i++) h3[i] = fmax3(w[i], w[i + 1], w[i + 2]);
}

__global__ __launch_bounds__(THREADS) void detection_head_kernel(
    const float* __restrict__ seg,   // [B, 2, H, W]
    float* __restrict__ out)         // [B*H*W] xnms | [B*2*H*W] seg copy
{
    const int b   = blockIdx.y;
    const int ty0 = blockIdx.x * R;
    const int wid  = threadIdx.x >> 5;
    const int lane = threadIdx.x & 31;
    const int gx   = wid * 128 + lane * 4;

    const float* __restrict__ c0 = seg + (size_t)b * 2 * H * W;
    const float* __restrict__ c1 = c0 + (size_t)H * W;
    float* __restrict__ oseg = out + (size_t)B * H * W + (size_t)b * 2 * H * W;
    float* __restrict__ oxn  = out + (size_t)b * H * W;

    // Rolling state: top row's horizontal 3-max, mid row's raw window + 3-max.
    float w_tmp[6], w_mid[6];
    float h3t[4], h3m[4];

    load_row(c0, c1, oseg, ty0 - 1, gx, lane, false, w_tmp);  // halo row, no copy
    h3_of(w_tmp, h3t);
    load_row(c0, c1, oseg, ty0, gx, lane, true, w_mid);       // first owned row
    h3_of(w_mid, h3m);

    #pragma unroll 4
    for (int yo = 0; yo < R; yo++) {
        const int y = ty0 + yo;
        float w_bot[6], h3b[4];
        // Bottom row: owned rows get copied; the y=ty0+R halo row does not
        // (it is the next CTA's first owned row).
        load_row(c0, c1, oseg, y + 1, gx, lane, (yo + 1 < R), w_bot);
        h3_of(w_bot, h3b);

        float4 o;
        float* op = &o.x;
        #pragma unroll
        for (int i = 0; i < 4; i++) {
            float m = fmax3(h3t[i], fmaxf(w_mid[i], w_mid[i + 2]), h3b[i]);
            m = fmaxf(m, 0.0f);
            const float x = w_mid[i + 1];
            op[i] = (x > m) ? x : 0.0f;
        }
        __stcs((float4*)(oxn + (size_t)y * W + gx), o);

        // rotate window
        #pragma unroll
        for (int i = 0; i < 4; i++) { h3t[i] = h3m[i]; h3m[i] = h3b[i]; }
        #pragma unroll
        for (int j = 0; j < 6; j++) w_mid[j] = w_bot[j];
    }
}

extern "C" void kernel_launch(void* const* d_in, const int* in_sizes, int n_in,
                              void* d_out, int out_size)
{
    const float* seg = (const float*)d_in[0];
    float* out = (float*)d_out;

    dim3 block(THREADS, 1, 1);
    dim3 grid(H / R, B, 1);  // 64 x 16 = 1024 CTAs
    detection_head_kernel<<<grid, block>>>(seg, out);
}

// round 5
// speedup vs baseline: 1.1601x; 1.1601x over previous
#include <cuda_runtime.h>
#include <cuda_bf16.h>
#include <cstdint>

#define EPS_F 0.01f

constexpr int B = 16;
constexpr int H = 1024;
constexpr int W = 1024;

// Tile: 128 cols x 32 rows per CTA. Block 32x8 = 256 threads.
// Each thread computes a 4-wide x 4-high output block. Warp = one thread-row.
constexpr int TX = 32;
constexpr int TY = 8;
constexpr int TILE_W = 128;
constexpr int TILE_H = 32;

// smem: rows ty0-1..ty0+32 (34), cols tx0-4..tx0+131 (136 = 34 float4)
constexpr int SH_H = TILE_H + 2;            // 34
constexpr int SH_W = 136;
constexpr int F4_PER_ROW = SH_W / 4;        // 34
constexpr int FILL_TASKS = SH_H * F4_PER_ROW;  // 1156

__device__ __forceinline__ float fmax3(float a, float b, float c) {
    return fmaxf(fmaxf(a, b), c);
}

// Read one smem row's 6-wide window for this lane: center LDS.128 + shfl halo.
__device__ __forceinline__ void read_sr(
    const float (*sx)[SH_W], int sr, int lc, int lane, float w[6])
{
    const unsigned FULL = 0xFFFFFFFFu;
    const float4 ce = *(const float4*)&sx[sr][lc + 4];
    float lft = __shfl_up_sync(FULL, ce.w, 1);
    float rgt = __shfl_down_sync(FULL, ce.x, 1);
    if (lane == 0)  lft = sx[sr][3];
    if (lane == 31) rgt = sx[sr][132];
    w[0] = lft;
    w[1] = ce.x; w[2] = ce.y; w[3] = ce.z; w[4] = ce.w;
    w[5] = rgt;
}

__global__ __launch_bounds__(TX * TY) void detection_head_kernel(
    const float* __restrict__ seg,   // [B, 2, H, W]
    float* __restrict__ out)         // [B*H*W] xnms | [B*2*H*W] seg copy
{
    __shared__ float sx[SH_H][SH_W];

    const int b   = blockIdx.z;
    const int ty0 = blockIdx.y * TILE_H;
    const int tx0 = blockIdx.x * TILE_W;

    const float* __restrict__ c0 = seg + (size_t)b * 2 * H * W;
    const float* __restrict__ c1 = c0 + (size_t)H * W;
    float* __restrict__ oseg = out + (size_t)B * H * W + (size_t)b * 2 * H * W;

    const int tid  = threadIdx.y * TX + threadIdx.x;
    const int lane = threadIdx.x;

    // ---- Fill smem with x = c1 - c0 - EPS (halo -> 0, exact: pool is
    // relu'd + zero-floored) AND stream the seg copy for interior pixels. ----
    #pragma unroll
    for (int idx = tid; idx < FILL_TASKS; idx += TX * TY) {
        const unsigned row = (unsigned)idx / F4_PER_ROW;       // 0..33
        const unsigned col = (unsigned)idx - row * F4_PER_ROW; // 0..33
        const int gy = ty0 - 1 + (int)row;
        const int gx = tx0 - 4 + (int)(col * 4);               // 16B aligned
        float4 v = make_float4(0.f, 0.f, 0.f, 0.f);
        if ((unsigned)gy < (unsigned)H && (unsigned)gx < (unsigned)W) {
            const size_t g = (size_t)gy * W + gx;
            const float4 a  = *(const float4*)(c0 + g);
            const float4 bb = *(const float4*)(c1 + g);
            v.x = bb.x - a.x - EPS_F;
            v.y = bb.y - a.y - EPS_F;
            v.z = bb.z - a.z - EPS_F;
            v.w = bb.w - a.w - EPS_F;
            // Interior of this CTA's tile: written exactly once chip-wide.
            if (row >= 1u && row <= (unsigned)TILE_H &&
                col >= 1u && col <= (unsigned)(TILE_W / 4)) {
                __stcs((float4*)(oseg + g), a);
                __stcs((float4*)(oseg + (size_t)H * W + g), bb);
            }
        }
        *(float4*)&sx[row][col * 4] = v;
    }
    __syncthreads();

    // ---- Compute: 4 output rows per thread, rolling 3-row window ----
    const int yr0 = threadIdx.y * 4;      // local row 0..28 (smem rows yr0..yr0+5)
    const int lc  = threadIdx.x * 4;      // local col 0..124

    float w_top[6], w_mid[6];
    read_sr(sx, yr0 + 0, lc, lane, w_top);
    read_sr(sx, yr0 + 1, lc, lane, w_mid);

    float h3t[4], h3m[4];
    #pragma unroll
    for (int i = 0; i < 4; i++) {
        h3t[i] = fmax3(w_top[i], w_top[i + 1], w_top[i + 2]);
        h3m[i] = fmax3(w_mid[i], w_mid[i + 1], w_mid[i + 2]);
    }

    const int gy0 = ty0 + yr0;
    const int gx  = tx0 + lc;
    float* __restrict__ oxn = out + (size_t)b * H * W;

    #pragma unroll
    for (int k = 0; k < 4; k++) {
        float w_bot[6], h3b[4];
        read_sr(sx, yr0 + k + 2, lc, lane, w_bot);
        #pragma unroll
        for (int i = 0; i < 4; i++)
            h3b[i] = fmax3(w_bot[i], w_bot[i + 1], w_bot[i + 2]);

        float4 o;
        float* op = &o.x;
        #pragma unroll
        for (int i = 0; i < 4; i++) {
            float m = fmax3(h3t[i], fmaxf(w_mid[i], w_mid[i + 2]), h3b[i]);
            m = fmaxf(m, 0.0f);
            const float x = w_mid[i + 1];
            op[i] = (x > m) ? x : 0.0f;
        }
        __stcs((float4*)(oxn + (size_t)(gy0 + k) * W + gx), o);

        #pragma unroll
        for (int i = 0; i < 4; i++) { h3t[i] = h3m[i]; h3m[i] = h3b[i]; }
        #pragma unroll
        for (int j = 0; j < 6; j++) w_mid[j] = w_bot[j];
    }
}

extern "C" void kernel_launch(void* const* d_in, const int* in_sizes, int n_in,
                              void* d_out, int out_size)
{
    const float* seg = (const float*)d_in[0];
    float* out = (float*)d_out;

    dim3 block(TX, TY, 1);
    dim3 grid(W / TILE_W, H / TILE_H, B);  // 8 x 32 x 16 = 4096 CTAs
    detection_head_kernel<<<grid, block>>>(seg, out);
}